// round 5
// baseline (speedup 1.0000x reference)
#include <cuda_runtime.h>
#include <cuda_bf16.h>
#include <cstdint>

// Problem: out[b,i,j] = Vx(i; t0,t2) * Vy(j; t1,t2), where
//   t = (x @ W1 + b1) @ W2 + b2  ==  x @ (W1@W2) + (b1@W2 + b2)   (pure linear)
// So collapse the [1024,512]x[512,3] weights into Weff[1024,3] once per launch,
// then the heavy pass is a skinny GEMV + boxcar rasterization: memory-bound.

#define MAX_D 1024
#define S 56
#define KSTEEP 10.0f

__device__ float g_w0[MAX_D];
__device__ float g_w1[MAX_D];
__device__ float g_w2[MAX_D];
__device__ float g_beff[3];

// ---------------------------------------------------------------------------
// Kernel A: Weff = W1 @ W2  (warp per output row d), beff = b1 @ W2 + b2.
// W1: [D,H] row-major, W2: [H,3] row-major.
// ---------------------------------------------------------------------------
__global__ void weff_kernel(const float* __restrict__ W1,
                            const float* __restrict__ b1,
                            const float* __restrict__ W2,
                            const float* __restrict__ b2,
                            int D, int H) {
    int warp = (blockIdx.x * blockDim.x + threadIdx.x) >> 5;
    int lane = threadIdx.x & 31;

    if (warp < D) {
        const float* row = W1 + (size_t)warp * H;
        float a0 = 0.f, a1 = 0.f, a2 = 0.f;
        for (int h = lane; h < H; h += 32) {
            float w = row[h];
            const float* w2 = W2 + h * 3;
            a0 = fmaf(w, w2[0], a0);
            a1 = fmaf(w, w2[1], a1);
            a2 = fmaf(w, w2[2], a2);
        }
        #pragma unroll
        for (int o = 16; o > 0; o >>= 1) {
            a0 += __shfl_xor_sync(0xffffffffu, a0, o);
            a1 += __shfl_xor_sync(0xffffffffu, a1, o);
            a2 += __shfl_xor_sync(0xffffffffu, a2, o);
        }
        if (lane == 0) {
            g_w0[warp] = a0;
            g_w1[warp] = a1;
            g_w2[warp] = a2;
        }
    }

    // beff: tiny serial reduction, 3 threads of block 0
    if (blockIdx.x == 0 && threadIdx.x < 3) {
        int c = threadIdx.x;
        float s = b2[c];
        for (int h = 0; h < H; h++)
            s = fmaf(b1[h], W2[h * 3 + c], s);
        g_beff[c] = s;
    }
}

// ---------------------------------------------------------------------------
// Kernel B: one warp per batch row.
//   t = x[row,:] @ Weff + beff   (warp-cooperative dot products)
//   out[row,i,j] = Vx[i] * Vy[j]
// ---------------------------------------------------------------------------
__device__ __forceinline__ float fsigmoid(float z) {
    // matches fp32 jax.nn.sigmoid to ~1e-6; saturates correctly for |z| large
    return 1.0f / (1.0f + __expf(-z));
}

__global__ __launch_bounds__(256) void boxcar_kernel(const float* __restrict__ x,
                                                     float* __restrict__ out,
                                                     int B, int D) {
    __shared__ float s_w0[MAX_D];
    __shared__ float s_w1[MAX_D];
    __shared__ float s_w2[MAX_D];

    for (int e = threadIdx.x; e < D; e += blockDim.x) {
        s_w0[e] = g_w0[e];
        s_w1[e] = g_w1[e];
        s_w2[e] = g_w2[e];
    }
    __syncthreads();

    const int lane = threadIdx.x & 31;
    const int wid  = threadIdx.x >> 5;
    const int row  = blockIdx.x * (blockDim.x >> 5) + wid;
    if (row >= B) return;

    // ---- skinny GEMV: 3 dot products over D, conflict-free smem weights ----
    const float* __restrict__ xr = x + (size_t)row * D;
    float a0 = 0.f, a1 = 0.f, a2 = 0.f;
    #pragma unroll 8
    for (int e = lane; e < D; e += 32) {
        float xv = xr[e];
        a0 = fmaf(xv, s_w0[e], a0);
        a1 = fmaf(xv, s_w1[e], a1);
        a2 = fmaf(xv, s_w2[e], a2);
    }
    #pragma unroll
    for (int o = 16; o > 0; o >>= 1) {
        a0 += __shfl_xor_sync(0xffffffffu, a0, o);
        a1 += __shfl_xor_sync(0xffffffffu, a1, o);
        a2 += __shfl_xor_sync(0xffffffffu, a2, o);
    }
    const float t0 = a0 + g_beff[0];   // x center (maps to i)
    const float t1 = a1 + g_beff[1];   // y center (maps to j)
    const float t2 = a2 + g_beff[2];   // size

    // ---- boxcar profiles: lane covers coords lane and lane+32 ----
    const float half = 0.5f * t2;
    const float c0 = (float)lane;
    const float c1 = (float)(lane + 32);

    float vx0 = fsigmoid(KSTEEP * (c0 - t0 + half)) - fsigmoid(KSTEEP * (c0 - t0 - half));
    float vy0 = fsigmoid(KSTEEP * (c0 - t1 + half)) - fsigmoid(KSTEEP * (c0 - t1 - half));
    float vx1 = 0.f, vy1 = 0.f;
    if (lane < S - 32) {
        vx1 = fsigmoid(KSTEEP * (c1 - t0 + half)) - fsigmoid(KSTEEP * (c1 - t0 - half));
        vy1 = fsigmoid(KSTEEP * (c1 - t1 + half)) - fsigmoid(KSTEEP * (c1 - t1 - half));
    }

    // ---- rasterize outer product: 56 rows of 56 contiguous floats ----
    float* __restrict__ orow = out + (size_t)row * (S * S);
    #pragma unroll
    for (int i = 0; i < S; i++) {
        float src = (i < 32) ? vx0 : vx1;
        float vxi = __shfl_sync(0xffffffffu, src, i & 31);
        orow[lane] = vxi * vy0;
        if (lane < S - 32)
            orow[lane + 32] = vxi * vy1;
        orow += S;
    }
}

// ---------------------------------------------------------------------------
// Launch. Inputs (metadata order): x[B,D], W1[D,H], b1[H], W2[H,3], b2[3].
// Output: float32 [B, 56, 56].
// ---------------------------------------------------------------------------
extern "C" void kernel_launch(void* const* d_in, const int* in_sizes, int n_in,
                              void* d_out, int out_size) {
    const float* x  = (const float*)d_in[0];
    const float* W1 = (const float*)d_in[1];
    const float* b1 = (const float*)d_in[2];
    const float* W2 = (const float*)d_in[3];
    const float* b2 = (const float*)d_in[4];
    float* out = (float*)d_out;

    const int H = in_sizes[2];           // 512
    const int D = in_sizes[1] / H;       // 1024
    const int B = in_sizes[0] / D;       // 16384

    // Kernel A: one warp per d-row of Weff
    {
        int warps = D;
        int threads = 256;
        int blocks = (warps * 32 + threads - 1) / threads;
        weff_kernel<<<blocks, threads>>>(W1, b1, W2, b2, D, H);
    }

    // Kernel B: one warp per batch row, 8 warps per block
    {
        int threads = 256;
        int rows_per_block = threads / 32;
        int blocks = (B + rows_per_block - 1) / rows_per_block;
        boxcar_kernel<<<blocks, threads>>>(x, out, B, D);
    }
}